// round 2
// baseline (speedup 1.0000x reference)
#include <cuda_runtime.h>
#include <math.h>

#define BSZ 8
#define SEQ 8192
#define DM  128
#define HH  128
#define NC  64      // chunks per sequence
#define CS  128     // chunk size (tokens)

typedef unsigned long long u64;

// ---------------- scratch (device globals; no allocation allowed) -----------
__device__ float g_at[BSZ * SEQ * HH];        // 33.5 MB
__device__ float g_bt[BSZ * SEQ * HH];        // 33.5 MB
__device__ float g_stA[2][BSZ][NC][HH];
__device__ float g_stB[2][BSZ][NC][HH];
__device__ float g_hin[2][BSZ][NC][HH];
__device__ float g_scalars[BSZ][6];           // s1,b1,g1,s2,b2,g2 per batch

__device__ __forceinline__ float sigmoidf_(float v) {
    return 1.f / (1.f + expf(-v));
}
__device__ __forceinline__ float geluf_(float v) {
    float u = v + 0.044715f * v * v * v;
    return 0.5f * v * (1.f + tanhf(0.7978845608028654f * u));
}

// ---------------- packed f32x2 helpers (FFMA2 path, sm_103a) ----------------
__device__ __forceinline__ u64 pk2(float v) {
    u64 r; asm("mov.b64 %0, {%1,%2};" : "=l"(r) : "f"(v), "f"(v)); return r;
}
__device__ __forceinline__ void upk(u64 v, float& lo, float& hi) {
    asm("mov.b64 {%0,%1}, %2;" : "=f"(lo), "=f"(hi) : "l"(v));
}
__device__ __forceinline__ u64 f2fma(u64 a, u64 b, u64 c) {
    u64 d; asm("fma.rn.f32x2 %0, %1, %2, %3;" : "=l"(d) : "l"(a), "l"(b), "l"(c));
    return d;
}
__device__ __forceinline__ u64 f2add(u64 a, u64 b) {
    u64 d; asm("add.rn.f32x2 %0, %1, %2;" : "=l"(d) : "l"(a), "l"(b));
    return d;
}

// ---------------- K0: per-batch conditioning scalars ------------------------
__global__ void k0_scalars(const float* __restrict__ c,
    const float* w0, const float* b0, const float* w1, const float* b1,
    const float* w2, const float* b2, const float* w3, const float* b3,
    const float* w4, const float* b4, const float* w5, const float* b5)
{
    __shared__ float red[128];
    int b = blockIdx.x, tid = threadIdx.x;
    float cv = c[b * 128 + tid];
    const float* ws[6] = {w0, w1, w2, w3, w4, w5};
    const float* bs[6] = {b0, b1, b2, b3, b4, b5};
    for (int j = 0; j < 6; j++) {
        red[tid] = cv * ws[j][tid];
        __syncthreads();
        for (int off = 64; off > 0; off >>= 1) {
            if (tid < off) red[tid] += red[tid + off];
            __syncthreads();
        }
        if (tid == 0) g_scalars[b][j] = red[0] + bs[j][0];
        __syncthreads();
    }
}

// ---------------- K1: LN -> LN -> (u, gates) -> a_t, b_t --------------------
__global__ __launch_bounds__(256) void k1_pre(
    const float* __restrict__ x,   const float* __restrict__ Win,
    const float* __restrict__ bin, const float* __restrict__ pos,
    const float* __restrict__ Wi,  const float* __restrict__ bi,
    const float* __restrict__ Wr,  const float* __restrict__ br,
    const float* __restrict__ avec)
{
    __shared__ float A[64][128];   // ln2h tile, later overwritten with u
    __shared__ float LA[128];
    int tid = threadIdx.x;
    int to  = blockIdx.x * 64;
    int b   = to >> 13;
    int tib = to & (SEQ - 1);
    if (tid < 128) LA[tid] = logf(avec[tid]);
    float s1  = g_scalars[b][0];
    float b1s = g_scalars[b][1];
    float alpha = 1.f + s1;

    // ---- stage 1: two layernorms (token handled by 4 threads, 32 ch each)
    {
        int tt = tid >> 2, q = tid & 3;
        const float4* xp = reinterpret_cast<const float4*>(x + (to + tt) * 128 + q * 32);
        float4 v[8];
#pragma unroll
        for (int i = 0; i < 8; i++) v[i] = xp[i];
        float s = 0.f, ss = 0.f;
#pragma unroll
        for (int i = 0; i < 8; i++) {
            s  += v[i].x + v[i].y + v[i].z + v[i].w;
            ss += v[i].x * v[i].x + v[i].y * v[i].y + v[i].z * v[i].z + v[i].w * v[i].w;
        }
        s  += __shfl_xor_sync(0xffffffffu, s, 1);
        s  += __shfl_xor_sync(0xffffffffu, s, 2);
        ss += __shfl_xor_sync(0xffffffffu, ss, 1);
        ss += __shfl_xor_sync(0xffffffffu, ss, 2);
        float m   = s * (1.f / 128.f);
        float var = ss * (1.f / 128.f) - m * m;
        float rs  = rsqrtf(var + 1e-6f);
        float s2 = 0.f, ss2 = 0.f;
#pragma unroll
        for (int i = 0; i < 8; i++) {
            v[i].x = fmaf(alpha, (v[i].x - m) * rs, b1s);
            v[i].y = fmaf(alpha, (v[i].y - m) * rs, b1s);
            v[i].z = fmaf(alpha, (v[i].z - m) * rs, b1s);
            v[i].w = fmaf(alpha, (v[i].w - m) * rs, b1s);
            s2  += v[i].x + v[i].y + v[i].z + v[i].w;
            ss2 += v[i].x * v[i].x + v[i].y * v[i].y + v[i].z * v[i].z + v[i].w * v[i].w;
        }
        s2  += __shfl_xor_sync(0xffffffffu, s2, 1);
        s2  += __shfl_xor_sync(0xffffffffu, s2, 2);
        ss2 += __shfl_xor_sync(0xffffffffu, ss2, 1);
        ss2 += __shfl_xor_sync(0xffffffffu, ss2, 2);
        float m2   = s2 * (1.f / 128.f);
        float var2 = ss2 * (1.f / 128.f) - m2 * m2;
        float rs2  = rsqrtf(var2 + 1e-6f);
        float4* Ap = reinterpret_cast<float4*>(&A[tt][q * 32]);
#pragma unroll
        for (int i = 0; i < 8; i++) {
            float4 o;
            o.x = (v[i].x - m2) * rs2; o.y = (v[i].y - m2) * rs2;
            o.z = (v[i].z - m2) * rs2; o.w = (v[i].w - m2) * rs2;
            Ap[i] = o;
        }
    }
    __syncthreads();

    // ---- stage 2: u = ln2h @ Win  (packed f32x2, 8 tok x 4 ch per thread)
    int tr = tid >> 5, tc = tid & 31;
    u64 acc[8][2];
#pragma unroll
    for (int i = 0; i < 8; i++) { acc[i][0] = 0ull; acc[i][1] = 0ull; }
    {
        const ulonglong2* W2 = reinterpret_cast<const ulonglong2*>(Win);
        for (int k = 0; k < 128; k++) {
            ulonglong2 w = W2[k * 32 + tc];
#pragma unroll
            for (int i = 0; i < 8; i++) {
                u64 a2 = pk2(A[tr * 8 + i][k]);
                acc[i][0] = f2fma(a2, w.x, acc[i][0]);
                acc[i][1] = f2fma(a2, w.y, acc[i][1]);
            }
        }
    }
    __syncthreads();
    // write u (acc + bias + pos_emb) back into A (packed)
    {
        ulonglong2 bv = reinterpret_cast<const ulonglong2*>(bin)[tc];
#pragma unroll
        for (int i = 0; i < 8; i++) {
            int t = tr * 8 + i;
            ulonglong2 pv = reinterpret_cast<const ulonglong2*>(pos + (tib + t) * 128)[tc];
            ulonglong2 o;
            o.x = f2add(f2add(acc[i][0], bv.x), pv.x);
            o.y = f2add(f2add(acc[i][1], bv.y), pv.y);
            *reinterpret_cast<ulonglong2*>(&A[t][tc * 4]) = o;
        }
    }
    __syncthreads();

    // ---- stage 3: gates (two packed GEMMs sharing a-fragment)
    u64 ai[8][2], ar[8][2];
#pragma unroll
    for (int i = 0; i < 8; i++) { ai[i][0] = ai[i][1] = 0ull; ar[i][0] = ar[i][1] = 0ull; }
    {
        const ulonglong2* Wi2 = reinterpret_cast<const ulonglong2*>(Wi);
        const ulonglong2* Wr2 = reinterpret_cast<const ulonglong2*>(Wr);
        for (int k = 0; k < 128; k++) {
            ulonglong2 wi = Wi2[k * 32 + tc];
            ulonglong2 wr = Wr2[k * 32 + tc];
#pragma unroll
            for (int i = 0; i < 8; i++) {
                u64 a2 = pk2(A[tr * 8 + i][k]);
                ai[i][0] = f2fma(a2, wi.x, ai[i][0]);
                ai[i][1] = f2fma(a2, wi.y, ai[i][1]);
                ar[i][0] = f2fma(a2, wr.x, ar[i][0]);
                ar[i][1] = f2fma(a2, wr.y, ar[i][1]);
            }
        }
    }
    float4 biv = reinterpret_cast<const float4*>(bi)[tc];
    float4 brv = reinterpret_cast<const float4*>(br)[tc];
    float la[4] = {LA[tc * 4 + 0], LA[tc * 4 + 1], LA[tc * 4 + 2], LA[tc * 4 + 3]};
    float bif[4] = {biv.x, biv.y, biv.z, biv.w};
    float brf[4] = {brv.x, brv.y, brv.z, brv.w};
#pragma unroll
    for (int i = 0; i < 8; i++) {
        int t = tr * 8 + i;
        float4 uv = *reinterpret_cast<const float4*>(&A[t][tc * 4]);
        float uf[4] = {uv.x, uv.y, uv.z, uv.w};
        float aif[4], arf[4];
        upk(ai[i][0], aif[0], aif[1]); upk(ai[i][1], aif[2], aif[3]);
        upk(ar[i][0], arf[0], arf[1]); upk(ar[i][1], arf[2], arf[3]);
        int idx = (to + t) * 128 + tc * 4;
        float av4[4], bv4[4];
#pragma unroll
        for (int j = 0; j < 4; j++) {
            float gi  = sigmoidf_(aif[j] + bif[j]);
            float gr  = sigmoidf_(arf[j] + brf[j]);
            float atv = expf(8.f * gr * la[j]);
            av4[j] = atv;
            bv4[j] = sqrtf(fmaxf(1.f - atv * atv, 0.f)) * gi * uf[j];
        }
        *reinterpret_cast<float4*>(g_at + idx) = make_float4(av4[0], av4[1], av4[2], av4[3]);
        *reinterpret_cast<float4*>(g_bt + idx) = make_float4(bv4[0], bv4[1], bv4[2], bv4[3]);
    }
}

// ---------------- K2a: per-chunk scan states (both directions) --------------
__global__ __launch_bounds__(256) void k2a_chunk()
{
    int blk = blockIdx.x;
    int b = blk >> 6, ci = blk & 63;
    int tid = threadIdx.x;
    int dir = tid >> 7, h = tid & 127;
    int base = ((b << 13) + (ci << 7)) * 128 + h;
    float Ap = 1.f, Bv = 0.f;
    if (dir == 0) {
#pragma unroll 4
        for (int s = 0; s < CS; s++) {
            int idx = base + (s << 7);
            float a = g_at[idx], bb = g_bt[idx];
            Ap *= a;
            Bv = fmaf(a, Bv, bb);
        }
    } else {
#pragma unroll 4
        for (int s = CS - 1; s >= 0; s--) {
            int idx = base + (s << 7);
            float a = g_at[idx], bb = g_bt[idx];
            Ap *= a;
            Bv = fmaf(a, Bv, bb);
        }
    }
    g_stA[dir][b][ci][h] = Ap;
    g_stB[dir][b][ci][h] = Bv;
}

// ---------------- K2b: chunk-level prefix scan (prefetch-all then chain) ----
__global__ __launch_bounds__(128) void k2b_prefix()
{
    int b = blockIdx.x & 7, dir = blockIdx.x >> 3;
    int h = threadIdx.x;
    float Av[NC], Bv[NC];
#pragma unroll
    for (int ci = 0; ci < NC; ci++) {
        Av[ci] = g_stA[dir][b][ci][h];
        Bv[ci] = g_stB[dir][b][ci][h];
    }
    float hin = 0.f;
    if (dir == 0) {
#pragma unroll
        for (int ci = 0; ci < NC; ci++) {
            g_hin[0][b][ci][h] = hin;
            hin = fmaf(Av[ci], hin, Bv[ci]);
        }
    } else {
#pragma unroll
        for (int ci = NC - 1; ci >= 0; ci--) {
            g_hin[1][b][ci][h] = hin;
            hin = fmaf(Av[ci], hin, Bv[ci]);
        }
    }
}

// ---------------- K3: re-scan chunk into smem + out-GEMM + gated residual ---
__global__ __launch_bounds__(256) void k3_scan_out(
    const float* __restrict__ x, const float* __restrict__ Wout,
    const float* __restrict__ bout, float* __restrict__ out)
{
    extern __shared__ float sm3[];
    float* HF = sm3;                // [128][128]
    float* HB = sm3 + 128 * 128;    // [128][128]
    int blk = blockIdx.x;
    int b = blk >> 6, ci = blk & 63;
    int tid = threadIdx.x;
    {
        int dir = tid >> 7, h = tid & 127;
        int base = ((b << 13) + (ci << 7)) * 128 + h;
        float hc = g_hin[dir][b][ci][h];
        if (dir == 0) {
#pragma unroll 4
            for (int s = 0; s < CS; s++) {
                int idx = base + (s << 7);
                hc = fmaf(g_at[idx], hc, g_bt[idx]);
                HF[(s << 7) + h] = hc;
            }
        } else {
#pragma unroll 4
            for (int s = CS - 1; s >= 0; s--) {
                int idx = base + (s << 7);
                hc = fmaf(g_at[idx], hc, g_bt[idx]);
                HB[(s << 7) + h] = hc;
            }
        }
    }
    __syncthreads();

    // GEMM (packed): r = HF @ Wout[0:128] + HB @ Wout[128:256]
    int r = tid >> 4, c = tid & 15;        // 8 tok x 8 ch per thread
    u64 acc[8][4];
#pragma unroll
    for (int i = 0; i < 8; i++)
#pragma unroll
        for (int j = 0; j < 4; j++) acc[i][j] = 0ull;
    const ulonglong2* W2 = reinterpret_cast<const ulonglong2*>(Wout);
    for (int k = 0; k < 128; k++) {
        ulonglong2 w0 = W2[k * 32 + c * 2];
        ulonglong2 w1 = W2[k * 32 + c * 2 + 1];
#pragma unroll
        for (int i = 0; i < 8; i++) {
            u64 a2 = pk2(HF[((r * 8 + i) << 7) + k]);
            acc[i][0] = f2fma(a2, w0.x, acc[i][0]);
            acc[i][1] = f2fma(a2, w0.y, acc[i][1]);
            acc[i][2] = f2fma(a2, w1.x, acc[i][2]);
            acc[i][3] = f2fma(a2, w1.y, acc[i][3]);
        }
    }
    for (int k = 0; k < 128; k++) {
        ulonglong2 w0 = W2[(128 + k) * 32 + c * 2];
        ulonglong2 w1 = W2[(128 + k) * 32 + c * 2 + 1];
#pragma unroll
        for (int i = 0; i < 8; i++) {
            u64 a2 = pk2(HB[((r * 8 + i) << 7) + k]);
            acc[i][0] = f2fma(a2, w0.x, acc[i][0]);
            acc[i][1] = f2fma(a2, w0.y, acc[i][1]);
            acc[i][2] = f2fma(a2, w1.x, acc[i][2]);
            acc[i][3] = f2fma(a2, w1.y, acc[i][3]);
        }
    }
    u64 g1p = pk2(g_scalars[b][2]);
    ulonglong2 boA = reinterpret_cast<const ulonglong2*>(bout)[c * 2];
    ulonglong2 boB = reinterpret_cast<const ulonglong2*>(bout)[c * 2 + 1];
#pragma unroll
    for (int i = 0; i < 8; i++) {
        int t = (b << 13) + (ci << 7) + r * 8 + i;
        const ulonglong2* xp = reinterpret_cast<const ulonglong2*>(x + t * 128 + c * 8);
        ulonglong2 x0 = xp[0], x1 = xp[1];
        ulonglong2 o0, o1;
        o0.x = f2fma(g1p, f2add(acc[i][0], boA.x), x0.x);
        o0.y = f2fma(g1p, f2add(acc[i][1], boA.y), x0.y);
        o1.x = f2fma(g1p, f2add(acc[i][2], boB.x), x1.x);
        o1.y = f2fma(g1p, f2add(acc[i][3], boB.y), x1.y);
        ulonglong2* op = reinterpret_cast<ulonglong2*>(out + t * 128 + c * 8);
        op[0] = o0;
        op[1] = o1;
    }
}

// ---------------- K4: conditioned LN -> GELU MLP -> gated residual ----------
__global__ __launch_bounds__(512) void k4_mlp(
    float* __restrict__ out, const float* __restrict__ W1,
    const float* __restrict__ b1v, const float* __restrict__ W2,
    const float* __restrict__ b2v)
{
    extern __shared__ float sm4[];
    float* HS = sm4;                 // [64][128]
    float* M1 = sm4 + 64 * 128;      // [64][512]
    int tid = threadIdx.x;
    int to = blockIdx.x * 64;
    int b = to >> 13;
    float s2 = g_scalars[b][3], b2s = g_scalars[b][4], g2 = g_scalars[b][5];
    float alpha = 1.f + s2;

    // LN: token handled by 8 threads, 16 ch each
    {
        int tt = tid >> 3, oc = tid & 7;
        const float4* xp = reinterpret_cast<const float4*>(out + (to + tt) * 128 + oc * 16);
        float4 v[4];
#pragma unroll
        for (int i = 0; i < 4; i++) v[i] = xp[i];
        float s = 0.f, ss = 0.f;
#pragma unroll
        for (int i = 0; i < 4; i++) {
            s  += v[i].x + v[i].y + v[i].z + v[i].w;
            ss += v[i].x * v[i].x + v[i].y * v[i].y + v[i].z * v[i].z + v[i].w * v[i].w;
        }
        s  += __shfl_xor_sync(0xffffffffu, s, 1);
        s  += __shfl_xor_sync(0xffffffffu, s, 2);
        s  += __shfl_xor_sync(0xffffffffu, s, 4);
        ss += __shfl_xor_sync(0xffffffffu, ss, 1);
        ss += __shfl_xor_sync(0xffffffffu, ss, 2);
        ss += __shfl_xor_sync(0xffffffffu, ss, 4);
        float m   = s * (1.f / 128.f);
        float var = ss * (1.f / 128.f) - m * m;
        float rs  = rsqrtf(var + 1e-6f);
        float4* hp = reinterpret_cast<float4*>(&HS[tt * 128 + oc * 16]);
#pragma unroll
        for (int i = 0; i < 4; i++) {
            float4 o;
            o.x = fmaf(alpha, (v[i].x - m) * rs, b2s);
            o.y = fmaf(alpha, (v[i].y - m) * rs, b2s);
            o.z = fmaf(alpha, (v[i].z - m) * rs, b2s);
            o.w = fmaf(alpha, (v[i].w - m) * rs, b2s);
            hp[i] = o;
        }
    }
    __syncthreads();

    // GEMM1 (packed): 64x512, k=128; tile 4 tok x 16 ch per thread
    int r = tid >> 5, c = tid & 31;
    u64 acc[4][8];
#pragma unroll
    for (int i = 0; i < 4; i++)
#pragma unroll
        for (int j = 0; j < 8; j++) acc[i][j] = 0ull;
    {
        const ulonglong2* W12 = reinterpret_cast<const ulonglong2*>(W1); // 128 per row
        for (int k = 0; k < 128; k++) {
            ulonglong2 w0 = W12[k * 128 + c * 4 + 0];
            ulonglong2 w1 = W12[k * 128 + c * 4 + 1];
            ulonglong2 w2 = W12[k * 128 + c * 4 + 2];
            ulonglong2 w3 = W12[k * 128 + c * 4 + 3];
#pragma unroll
            for (int i = 0; i < 4; i++) {
                u64 a2 = pk2(HS[(r * 4 + i) * 128 + k]);
                acc[i][0] = f2fma(a2, w0.x, acc[i][0]);
                acc[i][1] = f2fma(a2, w0.y, acc[i][1]);
                acc[i][2] = f2fma(a2, w1.x, acc[i][2]);
                acc[i][3] = f2fma(a2, w1.y, acc[i][3]);
                acc[i][4] = f2fma(a2, w2.x, acc[i][4]);
                acc[i][5] = f2fma(a2, w2.y, acc[i][5]);
                acc[i][6] = f2fma(a2, w3.x, acc[i][6]);
                acc[i][7] = f2fma(a2, w3.y, acc[i][7]);
            }
        }
    }
    // gelu + store m1
    {
        const float4* b1q = reinterpret_cast<const float4*>(b1v);
        float4 bb0 = b1q[c * 4 + 0], bb1 = b1q[c * 4 + 1];
        float4 bb2 = b1q[c * 4 + 2], bb3 = b1q[c * 4 + 3];
        float bias[16] = {bb0.x, bb0.y, bb0.z, bb0.w, bb1.x, bb1.y, bb1.z, bb1.w,
                          bb2.x, bb2.y, bb2.z, bb2.w, bb3.x, bb3.y, bb3.z, bb3.w};
#pragma unroll
        for (int i = 0; i < 4; i++) {
            float* mrow = &M1[(r * 4 + i) * 512 + c * 16];
#pragma unroll
            for (int j = 0; j < 8; j++) {
                float f0, f1;
                upk(acc[i][j], f0, f1);
                mrow[2 * j]     = geluf_(f0 + bias[2 * j]);
                mrow[2 * j + 1] = geluf_(f1 + bias[2 * j + 1]);
            }
        }
    }
    __syncthreads();

    // GEMM2 (packed): 64x128, k=512; tile 4 tok x 4 ch per thread
    u64 a2c[4][2];
#pragma unroll
    for (int i = 0; i < 4; i++) { a2c[i][0] = 0ull; a2c[i][1] = 0ull; }
    {
        const ulonglong2* W22 = reinterpret_cast<const ulonglong2*>(W2); // 32 per row
        for (int k = 0; k < 512; k++) {
            ulonglong2 w = W22[k * 32 + c];
#pragma unroll
            for (int i = 0; i < 4; i++) {
                u64 av2 = pk2(M1[(r * 4 + i) * 512 + k]);
                a2c[i][0] = f2fma(av2, w.x, a2c[i][0]);
                a2c[i][1] = f2fma(av2, w.y, a2c[i][1]);
            }
        }
    }
    u64 g2p = pk2(g2);
    ulonglong2 bb = reinterpret_cast<const ulonglong2*>(b2v)[c];
#pragma unroll
    for (int i = 0; i < 4; i++) {
        int t = to + r * 4 + i;
        ulonglong2* op = reinterpret_cast<ulonglong2*>(out + t * 128 + c * 4);
        ulonglong2 xv = *op;
        ulonglong2 o;
        o.x = f2fma(g2p, f2add(a2c[i][0], bb.x), xv.x);
        o.y = f2fma(g2p, f2add(a2c[i][1], bb.y), xv.y);
        *op = o;
    }
}

// ---------------- launch ----------------------------------------------------
extern "C" void kernel_launch(void* const* d_in, const int* in_sizes, int n_in,
                              void* d_out, int out_size)
{
    const float* x        = (const float*)d_in[0];
    const float* c        = (const float*)d_in[1];
    const float* cln1_sw  = (const float*)d_in[2];
    const float* cln1_sb  = (const float*)d_in[3];
    const float* cln1_bw  = (const float*)d_in[4];
    const float* cln1_bb  = (const float*)d_in[5];
    const float* gate1_w  = (const float*)d_in[6];
    const float* gate1_b  = (const float*)d_in[7];
    const float* rnn_in_w = (const float*)d_in[8];
    const float* rnn_in_b = (const float*)d_in[9];
    const float* pos_emb  = (const float*)d_in[10];
    const float* rnn_wi   = (const float*)d_in[11];
    const float* rnn_bi   = (const float*)d_in[12];
    const float* rnn_wr   = (const float*)d_in[13];
    const float* rnn_br   = (const float*)d_in[14];
    const float* rnn_a    = (const float*)d_in[15];
    const float* rnn_out_w= (const float*)d_in[16];
    const float* rnn_out_b= (const float*)d_in[17];
    const float* cln2_sw  = (const float*)d_in[18];
    const float* cln2_sb  = (const float*)d_in[19];
    const float* cln2_bw  = (const float*)d_in[20];
    const float* cln2_bb  = (const float*)d_in[21];
    const float* gate2_w  = (const float*)d_in[22];
    const float* gate2_b  = (const float*)d_in[23];
    const float* mlp_w1   = (const float*)d_in[24];
    const float* mlp_b1   = (const float*)d_in[25];
    const float* mlp_w2   = (const float*)d_in[26];
    const float* mlp_b2   = (const float*)d_in[27];
    float* out = (float*)d_out;

    cudaFuncSetAttribute(k3_scan_out, cudaFuncAttributeMaxDynamicSharedMemorySize, 131072);
    cudaFuncSetAttribute(k4_mlp,      cudaFuncAttributeMaxDynamicSharedMemorySize, 163840);

    k0_scalars<<<8, 128>>>(c,
        cln1_sw, cln1_sb, cln1_bw, cln1_bb, gate1_w, gate1_b,
        cln2_sw, cln2_sb, cln2_bw, cln2_bb, gate2_w, gate2_b);
    k1_pre<<<1024, 256>>>(x, rnn_in_w, rnn_in_b, pos_emb,
                          rnn_wi, rnn_bi, rnn_wr, rnn_br, rnn_a);
    k2a_chunk<<<512, 256>>>();
    k2b_prefix<<<16, 128>>>();
    k3_scan_out<<<512, 256, 131072>>>(x, rnn_out_w, rnn_out_b, out);
    k4_mlp<<<1024, 512, 163840>>>(out, mlp_w1, mlp_b1, mlp_w2, mlp_b2);
}

// round 3
// speedup vs baseline: 3.6507x; 3.6507x over previous
#include <cuda_runtime.h>
#include <math.h>
#include <stdint.h>

#define BSZ 8
#define SEQ 8192
#define NC  64
#define CS  128
#define SPAD 136

// ---------------- scratch -----------------------------------------------
__device__ float g_at[BSZ * SEQ * 128];
__device__ float g_bt[BSZ * SEQ * 128];
__device__ float g_stA[2][BSZ][NC][128];
__device__ float g_stB[2][BSZ][NC][128];
__device__ float g_hin[2][BSZ][NC][128];
__device__ float g_scalars[BSZ][6];

__device__ __forceinline__ float sigmoidf_(float v) {
    return 1.f / (1.f + expf(-v));
}
__device__ __forceinline__ float geluf_(float v) {
    float u = v + 0.044715f * v * v * v;
    return 0.5f * v * (1.f + tanhf(0.7978845608028654f * u));
}
__device__ __forceinline__ float cvt_tf32(float x) {
    uint32_t u;
    asm("cvt.rna.tf32.f32 %0, %1;" : "=r"(u) : "f"(x));
    return __uint_as_float(u);
}
__device__ __forceinline__ void mma_tf32(float c[4],
    uint32_t a0, uint32_t a1, uint32_t a2, uint32_t a3,
    uint32_t b0, uint32_t b1)
{
    asm("mma.sync.aligned.m16n8k8.row.col.f32.tf32.tf32.f32 "
        "{%0,%1,%2,%3},{%4,%5,%6,%7},{%8,%9},{%0,%1,%2,%3};"
        : "+f"(c[0]), "+f"(c[1]), "+f"(c[2]), "+f"(c[3])
        : "r"(a0), "r"(a1), "r"(a2), "r"(a3), "r"(b0), "r"(b1));
}

// stage a [128 x 128] fp32 block (row stride gstride floats) into smem
// (row stride SPAD), rounding to tf32. 256 threads.
__device__ __forceinline__ void stage128(float* Ws, const float* G,
                                         int gstride, int tid)
{
    for (int i = tid; i < 128 * 32; i += 256) {
        int r = i >> 5, c = (i & 31) << 2;
        float4 v = *reinterpret_cast<const float4*>(G + r * gstride + c);
        float4 o;
        o.x = cvt_tf32(v.x); o.y = cvt_tf32(v.y);
        o.z = cvt_tf32(v.z); o.w = cvt_tf32(v.w);
        *reinterpret_cast<float4*>(Ws + r * SPAD + c) = o;
    }
}

// warp computes a 16(row) x 64(col) tile of A[.. x 128] @ W[128 x ..],
// accumulating into c[8][4]. A rows at row0, W cols at col0.
__device__ __forceinline__ void gemm_16x64(const float* __restrict__ As,
    const float* __restrict__ Ws, int row0, int col0, int g, int t,
    float c[8][4])
{
#pragma unroll 4
    for (int k0 = 0; k0 < 128; k0 += 8) {
        const float* Ar = As + (row0 + g) * SPAD + k0 + t;
        uint32_t a0 = __float_as_uint(Ar[0]);
        uint32_t a2 = __float_as_uint(Ar[4]);
        uint32_t a1 = __float_as_uint(Ar[8 * SPAD]);
        uint32_t a3 = __float_as_uint(Ar[8 * SPAD + 4]);
        const float* Br = Ws + (k0 + t) * SPAD + col0 + g;
#pragma unroll
        for (int j = 0; j < 8; j++) {
            uint32_t b0 = __float_as_uint(Br[8 * j]);
            uint32_t b1 = __float_as_uint(Br[4 * SPAD + 8 * j]);
            mma_tf32(c[j], a0, a1, a2, a3, b0, b1);
        }
    }
}

// ---------------- K0: per-batch conditioning scalars ---------------------
__global__ void k0_scalars(const float* __restrict__ c,
    const float* w0, const float* b0, const float* w1, const float* b1,
    const float* w2, const float* b2, const float* w3, const float* b3,
    const float* w4, const float* b4, const float* w5, const float* b5)
{
    __shared__ float red[128];
    int b = blockIdx.x, tid = threadIdx.x;
    float cv = c[b * 128 + tid];
    const float* ws[6] = {w0, w1, w2, w3, w4, w5};
    const float* bs[6] = {b0, b1, b2, b3, b4, b5};
    for (int j = 0; j < 6; j++) {
        red[tid] = cv * ws[j][tid];
        __syncthreads();
        for (int off = 64; off > 0; off >>= 1) {
            if (tid < off) red[tid] += red[tid + off];
            __syncthreads();
        }
        if (tid == 0) g_scalars[b][j] = red[0] + bs[j][0];
        __syncthreads();
    }
}

// ---------------- K1: LN -> LN -> (u, gates) -> a_t,b_t (tensor mma) -----
__global__ __launch_bounds__(256) void k1_pre(
    const float* __restrict__ x,   const float* __restrict__ Win,
    const float* __restrict__ bin, const float* __restrict__ pos,
    const float* __restrict__ Wi,  const float* __restrict__ bi,
    const float* __restrict__ Wr,  const float* __restrict__ br,
    const float* __restrict__ avec)
{
    extern __shared__ float sm[];
    float* As  = sm;                           // 64 * SPAD (ln2h, then u)
    float* Ws  = sm + 64 * SPAD;               // 128 * SPAD
    float* L2A = sm + 64 * SPAD + 128 * SPAD;  // 128
    int tid = threadIdx.x;
    int to  = blockIdx.x * 64;
    int b   = to >> 13;
    int tib = to & (SEQ - 1);
    if (tid < 128) L2A[tid] = log2f(avec[tid]);
    float alpha = 1.f + g_scalars[b][0];
    float b1s   = g_scalars[b][1];

    // ---- LN x2 : 4 threads per token, 32 channels each
    {
        int tt = tid >> 2, q = tid & 3;
        const float4* xp = reinterpret_cast<const float4*>(x + (to + tt) * 128 + q * 32);
        float4 v[8];
#pragma unroll
        for (int i = 0; i < 8; i++) v[i] = xp[i];
        float s = 0.f, ss = 0.f;
#pragma unroll
        for (int i = 0; i < 8; i++) {
            s  += v[i].x + v[i].y + v[i].z + v[i].w;
            ss += v[i].x * v[i].x + v[i].y * v[i].y + v[i].z * v[i].z + v[i].w * v[i].w;
        }
        s  += __shfl_xor_sync(0xffffffffu, s, 1);
        s  += __shfl_xor_sync(0xffffffffu, s, 2);
        ss += __shfl_xor_sync(0xffffffffu, ss, 1);
        ss += __shfl_xor_sync(0xffffffffu, ss, 2);
        float m = s * (1.f / 128.f);
        float rs = rsqrtf(ss * (1.f / 128.f) - m * m + 1e-6f);
        float s2 = 0.f, ss2 = 0.f;
#pragma unroll
        for (int i = 0; i < 8; i++) {
            v[i].x = fmaf(alpha, (v[i].x - m) * rs, b1s);
            v[i].y = fmaf(alpha, (v[i].y - m) * rs, b1s);
            v[i].z = fmaf(alpha, (v[i].z - m) * rs, b1s);
            v[i].w = fmaf(alpha, (v[i].w - m) * rs, b1s);
            s2  += v[i].x + v[i].y + v[i].z + v[i].w;
            ss2 += v[i].x * v[i].x + v[i].y * v[i].y + v[i].z * v[i].z + v[i].w * v[i].w;
        }
        s2  += __shfl_xor_sync(0xffffffffu, s2, 1);
        s2  += __shfl_xor_sync(0xffffffffu, s2, 2);
        ss2 += __shfl_xor_sync(0xffffffffu, ss2, 1);
        ss2 += __shfl_xor_sync(0xffffffffu, ss2, 2);
        float m2 = s2 * (1.f / 128.f);
        float rs2 = rsqrtf(ss2 * (1.f / 128.f) - m2 * m2 + 1e-6f);
        float* Ap = &As[tt * SPAD + q * 32];
#pragma unroll
        for (int i = 0; i < 8; i++) {
            float4 o;
            o.x = cvt_tf32((v[i].x - m2) * rs2);
            o.y = cvt_tf32((v[i].y - m2) * rs2);
            o.z = cvt_tf32((v[i].z - m2) * rs2);
            o.w = cvt_tf32((v[i].w - m2) * rs2);
            *reinterpret_cast<float4*>(Ap + i * 4) = o;
        }
    }
    stage128(Ws, Win, 128, tid);
    __syncthreads();

    int lane = tid & 31, wid = tid >> 5;
    int g = lane >> 2, t = lane & 3;
    int wm = wid >> 1, wn = wid & 1;
    int row0 = wm * 16, col0 = wn * 64;

    // GEMM1: u = ln2h @ Win
    float c1[8][4];
#pragma unroll
    for (int j = 0; j < 8; j++)
#pragma unroll
        for (int e = 0; e < 4; e++) c1[j][e] = 0.f;
    gemm_16x64(As, Ws, row0, col0, g, t, c1);
    __syncthreads();

    // u = c1 + bin + pos  -> back into As (tf32)
#pragma unroll
    for (int j = 0; j < 8; j++) {
        int n = col0 + 8 * j + 2 * t;
        int r0 = row0 + g, r1 = r0 + 8;
        float2 bb = *reinterpret_cast<const float2*>(bin + n);
        float2 p0 = *reinterpret_cast<const float2*>(pos + (tib + r0) * 128 + n);
        float2 p1 = *reinterpret_cast<const float2*>(pos + (tib + r1) * 128 + n);
        As[r0 * SPAD + n]     = cvt_tf32(c1[j][0] + bb.x + p0.x);
        As[r0 * SPAD + n + 1] = cvt_tf32(c1[j][1] + bb.y + p0.y);
        As[r1 * SPAD + n]     = cvt_tf32(c1[j][2] + bb.x + p1.x);
        As[r1 * SPAD + n + 1] = cvt_tf32(c1[j][3] + bb.y + p1.y);
    }
    stage128(Ws, Wi, 128, tid);
    __syncthreads();

    // GEMM2: input gate
    float gi[8][4];
#pragma unroll
    for (int j = 0; j < 8; j++)
#pragma unroll
        for (int e = 0; e < 4; e++) gi[j][e] = 0.f;
    gemm_16x64(As, Ws, row0, col0, g, t, gi);
#pragma unroll
    for (int j = 0; j < 8; j++) {
        int n = col0 + 8 * j + 2 * t;
        float2 bb = *reinterpret_cast<const float2*>(bi + n);
        gi[j][0] = sigmoidf_(gi[j][0] + bb.x);
        gi[j][1] = sigmoidf_(gi[j][1] + bb.y);
        gi[j][2] = sigmoidf_(gi[j][2] + bb.x);
        gi[j][3] = sigmoidf_(gi[j][3] + bb.y);
    }
    __syncthreads();
    stage128(Ws, Wr, 128, tid);
    __syncthreads();

    // GEMM3: recurrence gate (reuse c1)
#pragma unroll
    for (int j = 0; j < 8; j++)
#pragma unroll
        for (int e = 0; e < 4; e++) c1[j][e] = 0.f;
    gemm_16x64(As, Ws, row0, col0, g, t, c1);

    // epilogue: a_t, b_t
#pragma unroll
    for (int j = 0; j < 8; j++) {
        int n = col0 + 8 * j + 2 * t;
        int r0 = row0 + g, r1 = r0 + 8;
        float2 bb = *reinterpret_cast<const float2*>(br + n);
        float la0 = L2A[n], la1 = L2A[n + 1];
        float u00 = As[r0 * SPAD + n], u01 = As[r0 * SPAD + n + 1];
        float u10 = As[r1 * SPAD + n], u11 = As[r1 * SPAD + n + 1];
        float at00 = exp2f(8.f * sigmoidf_(c1[j][0] + bb.x) * la0);
        float at01 = exp2f(8.f * sigmoidf_(c1[j][1] + bb.y) * la1);
        float at10 = exp2f(8.f * sigmoidf_(c1[j][2] + bb.x) * la0);
        float at11 = exp2f(8.f * sigmoidf_(c1[j][3] + bb.y) * la1);
        float bt00 = sqrtf(fmaxf(1.f - at00 * at00, 0.f)) * gi[j][0] * u00;
        float bt01 = sqrtf(fmaxf(1.f - at01 * at01, 0.f)) * gi[j][1] * u01;
        float bt10 = sqrtf(fmaxf(1.f - at10 * at10, 0.f)) * gi[j][2] * u10;
        float bt11 = sqrtf(fmaxf(1.f - at11 * at11, 0.f)) * gi[j][3] * u11;
        int i0 = (to + r0) * 128 + n;
        int i1 = (to + r1) * 128 + n;
        *reinterpret_cast<float2*>(g_at + i0) = make_float2(at00, at01);
        *reinterpret_cast<float2*>(g_at + i1) = make_float2(at10, at11);
        *reinterpret_cast<float2*>(g_bt + i0) = make_float2(bt00, bt01);
        *reinterpret_cast<float2*>(g_bt + i1) = make_float2(bt10, bt11);
    }
}

// ---------------- K2a: per-chunk scan states -----------------------------
__global__ __launch_bounds__(256) void k2a_chunk()
{
    int blk = blockIdx.x;
    int b = blk >> 6, ci = blk & 63;
    int tid = threadIdx.x;
    int dir = tid >> 7, h = tid & 127;
    int base = ((b << 13) + (ci << 7)) * 128 + h;
    float Ap = 1.f, Bv = 0.f;
    if (dir == 0) {
#pragma unroll 4
        for (int s = 0; s < CS; s++) {
            int idx = base + (s << 7);
            float a = g_at[idx], bb = g_bt[idx];
            Ap *= a;
            Bv = fmaf(a, Bv, bb);
        }
    } else {
#pragma unroll 4
        for (int s = CS - 1; s >= 0; s--) {
            int idx = base + (s << 7);
            float a = g_at[idx], bb = g_bt[idx];
            Ap *= a;
            Bv = fmaf(a, Bv, bb);
        }
    }
    g_stA[dir][b][ci][h] = Ap;
    g_stB[dir][b][ci][h] = Bv;
}

// ---------------- K2b: chunk-level prefix scan (prefetch then chain) -----
__global__ __launch_bounds__(128) void k2b_prefix()
{
    int b = blockIdx.x & 7, dir = blockIdx.x >> 3;
    int h = threadIdx.x;
    float Av[NC], Bv[NC];
#pragma unroll
    for (int ci = 0; ci < NC; ci++) {
        Av[ci] = g_stA[dir][b][ci][h];
        Bv[ci] = g_stB[dir][b][ci][h];
    }
    float hin = 0.f;
    if (dir == 0) {
#pragma unroll
        for (int ci = 0; ci < NC; ci++) {
            g_hin[0][b][ci][h] = hin;
            hin = fmaf(Av[ci], hin, Bv[ci]);
        }
    } else {
#pragma unroll
        for (int ci = NC - 1; ci >= 0; ci--) {
            g_hin[1][b][ci][h] = hin;
            hin = fmaf(Av[ci], hin, Bv[ci]);
        }
    }
}

// ---------------- K3: re-scan + out-GEMM (tensor mma) + residual ---------
__global__ __launch_bounds__(256) void k3_scan_out(
    const float* __restrict__ x, const float* __restrict__ Wout,
    const float* __restrict__ bout, float* __restrict__ out)
{
    extern __shared__ float sm[];
    float* HF = sm;                   // 128 * SPAD
    float* HB = sm + 128 * SPAD;      // 128 * SPAD
    float* Ws = sm + 256 * SPAD;      // 128 * SPAD
    int blk = blockIdx.x;
    int b = blk >> 6, ci = blk & 63;
    int tid = threadIdx.x;
    {
        int dir = tid >> 7, h = tid & 127;
        int base = ((b << 13) + (ci << 7)) * 128 + h;
        float hc = g_hin[dir][b][ci][h];
        if (dir == 0) {
#pragma unroll 4
            for (int s = 0; s < CS; s++) {
                int idx = base + (s << 7);
                hc = fmaf(g_at[idx], hc, g_bt[idx]);
                HF[s * SPAD + h] = cvt_tf32(hc);
            }
        } else {
#pragma unroll 4
            for (int s = CS - 1; s >= 0; s--) {
                int idx = base + (s << 7);
                hc = fmaf(g_at[idx], hc, g_bt[idx]);
                HB[s * SPAD + h] = cvt_tf32(hc);
            }
        }
    }
    stage128(Ws, Wout, 128, tid);
    __syncthreads();

    int lane = tid & 31, wid = tid >> 5;
    int g = lane >> 2, t = lane & 3;
    int wm = wid >> 1, wn = wid & 1;
    int row0 = wm * 32, col0 = wn * 64;
    float c[2][8][4];
#pragma unroll
    for (int m = 0; m < 2; m++)
#pragma unroll
        for (int j = 0; j < 8; j++)
#pragma unroll
            for (int e = 0; e < 4; e++) c[m][j][e] = 0.f;
#pragma unroll
    for (int m = 0; m < 2; m++)
        gemm_16x64(HF, Ws, row0 + 16 * m, col0, g, t, c[m]);
    __syncthreads();
    stage128(Ws, Wout + 128 * 128, 128, tid);
    __syncthreads();
#pragma unroll
    for (int m = 0; m < 2; m++)
        gemm_16x64(HB, Ws, row0 + 16 * m, col0, g, t, c[m]);

    float g1 = g_scalars[b][2];
    int tbase = (b << 13) + (ci << 7);
#pragma unroll
    for (int m = 0; m < 2; m++) {
#pragma unroll
        for (int j = 0; j < 8; j++) {
            int n = col0 + 8 * j + 2 * t;
            int r0 = row0 + 16 * m + g, r1 = r0 + 8;
            float2 bb = *reinterpret_cast<const float2*>(bout + n);
            int i0 = (tbase + r0) * 128 + n;
            int i1 = (tbase + r1) * 128 + n;
            float2 x0 = *reinterpret_cast<const float2*>(x + i0);
            float2 x1 = *reinterpret_cast<const float2*>(x + i1);
            float2 o0, o1;
            o0.x = fmaf(g1, c[m][j][0] + bb.x, x0.x);
            o0.y = fmaf(g1, c[m][j][1] + bb.y, x0.y);
            o1.x = fmaf(g1, c[m][j][2] + bb.x, x1.x);
            o1.y = fmaf(g1, c[m][j][3] + bb.y, x1.y);
            *reinterpret_cast<float2*>(out + i0) = o0;
            *reinterpret_cast<float2*>(out + i1) = o1;
        }
    }
}

// ---------------- K4: cond-LN -> GELU MLP (tensor mma) -> residual -------
__global__ __launch_bounds__(256) void k4_mlp(
    float* __restrict__ out, const float* __restrict__ W1,
    const float* __restrict__ b1v, const float* __restrict__ W2,
    const float* __restrict__ b2v)
{
    extern __shared__ float sm[];
    float* HS  = sm;                  // 64 * SPAD
    float* M1c = sm + 64 * SPAD;      // 64 * SPAD
    float* W1s = sm + 128 * SPAD;     // 128 * SPAD
    float* W2s = sm + 256 * SPAD;     // 128 * SPAD
    int tid = threadIdx.x;
    int to = blockIdx.x * 64;
    int b = to >> 13;
    float alpha = 1.f + g_scalars[b][3];
    float b2s = g_scalars[b][4], g2 = g_scalars[b][5];

    // LN: 4 threads per token
    {
        int tt = tid >> 2, q = tid & 3;
        const float4* xp = reinterpret_cast<const float4*>(out + (to + tt) * 128 + q * 32);
        float4 v[8];
#pragma unroll
        for (int i = 0; i < 8; i++) v[i] = xp[i];
        float s = 0.f, ss = 0.f;
#pragma unroll
        for (int i = 0; i < 8; i++) {
            s  += v[i].x + v[i].y + v[i].z + v[i].w;
            ss += v[i].x * v[i].x + v[i].y * v[i].y + v[i].z * v[i].z + v[i].w * v[i].w;
        }
        s  += __shfl_xor_sync(0xffffffffu, s, 1);
        s  += __shfl_xor_sync(0xffffffffu, s, 2);
        ss += __shfl_xor_sync(0xffffffffu, ss, 1);
        ss += __shfl_xor_sync(0xffffffffu, ss, 2);
        float m = s * (1.f / 128.f);
        float rs = rsqrtf(ss * (1.f / 128.f) - m * m + 1e-6f);
        float* hp = &HS[tt * SPAD + q * 32];
#pragma unroll
        for (int i = 0; i < 8; i++) {
            float4 o;
            o.x = cvt_tf32(fmaf(alpha, (v[i].x - m) * rs, b2s));
            o.y = cvt_tf32(fmaf(alpha, (v[i].y - m) * rs, b2s));
            o.z = cvt_tf32(fmaf(alpha, (v[i].z - m) * rs, b2s));
            o.w = cvt_tf32(fmaf(alpha, (v[i].w - m) * rs, b2s));
            *reinterpret_cast<float4*>(hp + i * 4) = o;
        }
    }

    int lane = tid & 31, wid = tid >> 5;
    int g = lane >> 2, t = lane & 3;
    int wm = wid >> 1, wn = wid & 1;
    int row0 = wm * 16, col0 = wn * 64;

    float C2[8][4];
#pragma unroll
    for (int j = 0; j < 8; j++)
#pragma unroll
        for (int e = 0; e < 4; e++) C2[j][e] = 0.f;

    for (int ch = 0; ch < 4; ch++) {
        __syncthreads();   // prior readers of W1s/W2s/M1c done; HS ready (ch=0)
        stage128(W1s, W1 + ch * 128, 512, tid);
        stage128(W2s, W2 + ch * 128 * 128, 128, tid);
        __syncthreads();

        float c1[8][4];
#pragma unroll
        for (int j = 0; j < 8; j++)
#pragma unroll
            for (int e = 0; e < 4; e++) c1[j][e] = 0.f;
        gemm_16x64(HS, W1s, row0, col0, g, t, c1);

        // gelu -> M1c (tf32)
#pragma unroll
        for (int j = 0; j < 8; j++) {
            int n = col0 + 8 * j + 2 * t;
            int r0 = row0 + g, r1 = r0 + 8;
            float2 bb = *reinterpret_cast<const float2*>(b1v + ch * 128 + n);
            M1c[r0 * SPAD + n]     = cvt_tf32(geluf_(c1[j][0] + bb.x));
            M1c[r0 * SPAD + n + 1] = cvt_tf32(geluf_(c1[j][1] + bb.y));
            M1c[r1 * SPAD + n]     = cvt_tf32(geluf_(c1[j][2] + bb.x));
            M1c[r1 * SPAD + n + 1] = cvt_tf32(geluf_(c1[j][3] + bb.y));
        }
        __syncthreads();
        gemm_16x64(M1c, W2s, row0, col0, g, t, C2);
    }

    // epilogue (in-place gated residual)
#pragma unroll
    for (int j = 0; j < 8; j++) {
        int n = col0 + 8 * j + 2 * t;
        int r0 = row0 + g, r1 = r0 + 8;
        float2 bb = *reinterpret_cast<const float2*>(b2v + n);
        int i0 = (to + r0) * 128 + n;
        int i1 = (to + r1) * 128 + n;
        float2 x0 = *reinterpret_cast<const float2*>(out + i0);
        float2 x1 = *reinterpret_cast<const float2*>(out + i1);
        float2 o0, o1;
        o0.x = fmaf(g2, C2[j][0] + bb.x, x0.x);
        o0.y = fmaf(g2, C2[j][1] + bb.y, x0.y);
        o1.x = fmaf(g2, C2[j][2] + bb.x, x1.x);
        o1.y = fmaf(g2, C2[j][3] + bb.y, x1.y);
        *reinterpret_cast<float2*>(out + i0) = o0;
        *reinterpret_cast<float2*>(out + i1) = o1;
    }
}

// ---------------- launch -------------------------------------------------
extern "C" void kernel_launch(void* const* d_in, const int* in_sizes, int n_in,
                              void* d_out, int out_size)
{
    const float* x        = (const float*)d_in[0];
    const float* c        = (const float*)d_in[1];
    const float* cln1_sw  = (const float*)d_in[2];
    const float* cln1_sb  = (const float*)d_in[3];
    const float* cln1_bw  = (const float*)d_in[4];
    const float* cln1_bb  = (const float*)d_in[5];
    const float* gate1_w  = (const float*)d_in[6];
    const float* gate1_b  = (const float*)d_in[7];
    const float* rnn_in_w = (const float*)d_in[8];
    const float* rnn_in_b = (const float*)d_in[9];
    const float* pos_emb  = (const float*)d_in[10];
    const float* rnn_wi   = (const float*)d_in[11];
    const float* rnn_bi   = (const float*)d_in[12];
    const float* rnn_wr   = (const float*)d_in[13];
    const float* rnn_br   = (const float*)d_in[14];
    const float* rnn_a    = (const float*)d_in[15];
    const float* rnn_out_w= (const float*)d_in[16];
    const float* rnn_out_b= (const float*)d_in[17];
    const float* cln2_sw  = (const float*)d_in[18];
    const float* cln2_sb  = (const float*)d_in[19];
    const float* cln2_bw  = (const float*)d_in[20];
    const float* cln2_bb  = (const float*)d_in[21];
    const float* gate2_w  = (const float*)d_in[22];
    const float* gate2_b  = (const float*)d_in[23];
    const float* mlp_w1   = (const float*)d_in[24];
    const float* mlp_b1   = (const float*)d_in[25];
    const float* mlp_w2   = (const float*)d_in[26];
    const float* mlp_b2   = (const float*)d_in[27];
    float* out = (float*)d_out;

    const int SM1 = (64 * SPAD + 128 * SPAD + 128) * 4;   // k1: ~105 KB
    const int SM3 = (3 * 128 * SPAD) * 4;                 // k3/k4: ~209 KB
    cudaFuncSetAttribute(k1_pre,      cudaFuncAttributeMaxDynamicSharedMemorySize, SM1);
    cudaFuncSetAttribute(k3_scan_out, cudaFuncAttributeMaxDynamicSharedMemorySize, SM3);
    cudaFuncSetAttribute(k4_mlp,      cudaFuncAttributeMaxDynamicSharedMemorySize, SM3);

    k0_scalars<<<8, 128>>>(c,
        cln1_sw, cln1_sb, cln1_bw, cln1_bb, gate1_w, gate1_b,
        cln2_sw, cln2_sb, cln2_bw, cln2_bb, gate2_w, gate2_b);
    k1_pre<<<1024, 256, SM1>>>(x, rnn_in_w, rnn_in_b, pos_emb,
                               rnn_wi, rnn_bi, rnn_wr, rnn_br, rnn_a);
    k2a_chunk<<<512, 256>>>();
    k2b_prefix<<<16, 128>>>();
    k3_scan_out<<<512, 256, SM3>>>(x, rnn_out_w, rnn_out_b, out);
    k4_mlp<<<1024, 256, SM3>>>(out, mlp_w1, mlp_b1, mlp_w2, mlp_b2);
}

// round 4
// speedup vs baseline: 4.1125x; 1.1265x over previous
#include <cuda_runtime.h>
#include <math.h>
#include <stdint.h>

#define BSZ 8
#define SEQ 8192
#define NC  64
#define CS  128
#define SPAD 136

// ---------------- scratch -----------------------------------------------
__device__ float g_at[BSZ * SEQ * 128];
__device__ float g_bt[BSZ * SEQ * 128];
__device__ float g_stA[2][BSZ][NC][128];
__device__ float g_stB[2][BSZ][NC][128];
// fragment-pair weight images: [seg][kstep(16)][ntile(16)][lane(32)] float2
// segs: 0 Win, 1 Wi, 2 Wr, 3 WoutF, 4 WoutB, 5-8 W1 chunks, 9-12 W2 chunks
__device__ float2 g_wimg[13][8192];

__device__ __forceinline__ float sigmoidf_(float v) {
    return 1.f / (1.f + expf(-v));
}
__device__ __forceinline__ float geluf_(float v) {
    float u = v + 0.044715f * v * v * v;
    return 0.5f * v * (1.f + tanhf(0.7978845608028654f * u));
}
__device__ __forceinline__ float cvt_tf32(float x) {
    uint32_t u;
    asm("cvt.rna.tf32.f32 %0, %1;" : "=r"(u) : "f"(x));
    return __uint_as_float(u);
}
__device__ __forceinline__ void mma_tf32(float c[4],
    uint32_t a0, uint32_t a1, uint32_t a2, uint32_t a3,
    uint32_t b0, uint32_t b1)
{
    asm("mma.sync.aligned.m16n8k8.row.col.f32.tf32.tf32.f32 "
        "{%0,%1,%2,%3},{%4,%5,%6,%7},{%8,%9},{%0,%1,%2,%3};"
        : "+f"(c[0]), "+f"(c[1]), "+f"(c[2]), "+f"(c[3])
        : "r"(a0), "r"(a1), "r"(a2), "r"(a3), "r"(b0), "r"(b1));
}

// dot(c[128], w[128]) by 32 threads (tid<32); returns full value in lane 0.
__device__ __forceinline__ float dot32(const float* cvec, const float* w, int tid)
{
    float4 cv = reinterpret_cast<const float4*>(cvec)[tid];
    float4 wv = reinterpret_cast<const float4*>(w)[tid];
    float p = cv.x * wv.x + cv.y * wv.y + cv.z * wv.z + cv.w * wv.w;
    p += __shfl_xor_sync(0xffffffffu, p, 16);
    p += __shfl_xor_sync(0xffffffffu, p, 8);
    p += __shfl_xor_sync(0xffffffffu, p, 4);
    p += __shfl_xor_sync(0xffffffffu, p, 2);
    p += __shfl_xor_sync(0xffffffffu, p, 1);
    return p;
}

// copy one 64KB weight image (8192 float2) gmem -> smem
__device__ __forceinline__ void copy_img(float2* dst, const float2* src, int tid)
{
    const float4* s4 = reinterpret_cast<const float4*>(src);
    float4* d4 = reinterpret_cast<float4*>(dst);
#pragma unroll 4
    for (int i = tid; i < 4096; i += 256) d4[i] = s4[i];
}

// warp computes 16(row) x 64(col) tile of A[..x128] @ W[128x..] with B from
// fragment-pair image. c[8][4] accumulated.
__device__ __forceinline__ void gemm_16x64_p(const float* __restrict__ As,
    const float2* __restrict__ Bimg, int row0, int wn, int lane, int g, int t,
    float c[8][4])
{
#pragma unroll 4
    for (int ks = 0; ks < 16; ks++) {
        const float* Ar = As + (row0 + g) * SPAD + ks * 8 + t;
        uint32_t a0 = __float_as_uint(Ar[0]);
        uint32_t a2 = __float_as_uint(Ar[4]);
        uint32_t a1 = __float_as_uint(Ar[8 * SPAD]);
        uint32_t a3 = __float_as_uint(Ar[8 * SPAD + 4]);
        const float2* Bw = Bimg + ((ks * 16 + wn * 8) << 5) + lane;
#pragma unroll
        for (int j = 0; j < 8; j++) {
            float2 bv = Bw[j << 5];
            mma_tf32(c[j], a0, a1, a2, a3,
                     __float_as_uint(bv.x), __float_as_uint(bv.y));
        }
    }
}

// ---------------- KP: pack all weights into fragment-pair images ---------
__global__ __launch_bounds__(256) void kp_pack(
    const float* __restrict__ Win, const float* __restrict__ Wi,
    const float* __restrict__ Wr,  const float* __restrict__ Wout,
    const float* __restrict__ W1,  const float* __restrict__ W2)
{
    int seg = blockIdx.x;
    const float* src;
    int ns;
    if (seg == 0)      { src = Win;  ns = 128; }
    else if (seg == 1) { src = Wi;   ns = 128; }
    else if (seg == 2) { src = Wr;   ns = 128; }
    else if (seg == 3) { src = Wout; ns = 128; }
    else if (seg == 4) { src = Wout + 128 * 128; ns = 128; }
    else if (seg < 9)  { src = W1 + (seg - 5) * 128; ns = 512; }
    else               { src = W2 + (seg - 9) * 128 * 128; ns = 128; }
    float2* dst = g_wimg[seg];
    for (int p = threadIdx.x; p < 8192; p += 256) {
        int lane = p & 31, nt = (p >> 5) & 15, ks = p >> 9;
        int g = lane >> 2, t = lane & 3;
        int k = ks * 8 + t, n = nt * 8 + g;
        dst[p] = make_float2(cvt_tf32(src[k * ns + n]),
                             cvt_tf32(src[(k + 4) * ns + n]));
    }
}

// ---------------- K1: LN -> LN -> (u, gates) -> a_t,b_t ------------------
__global__ __launch_bounds__(256) void k1_pre(
    const float* __restrict__ x,   const float* __restrict__ cvec,
    const float* __restrict__ sw1, const float* __restrict__ sb1,
    const float* __restrict__ bw1, const float* __restrict__ bb1,
    const float* __restrict__ bin, const float* __restrict__ pos,
    const float* __restrict__ bi,  const float* __restrict__ br,
    const float* __restrict__ avec)
{
    extern __shared__ float sm[];
    float*  As   = sm;                                  // 64*SPAD floats
    float2* Wimg = reinterpret_cast<float2*>(sm + 64 * SPAD);  // 8192 float2
    float*  L2A  = sm + 64 * SPAD + 16384;              // 128
    float*  sS   = L2A + 128;                           // 2
    int tid = threadIdx.x;
    int to  = blockIdx.x * 64;
    int b   = to >> 13;
    int tib = to & (SEQ - 1);

    if (tid < 32) {
        float p0 = dot32(cvec + b * 128, sw1, tid);
        float p1 = dot32(cvec + b * 128, bw1, tid);
        if (tid == 0) { sS[0] = p0 + sb1[0]; sS[1] = p1 + bb1[0]; }
    }
    if (tid < 128) L2A[tid] = log2f(avec[tid]);
    __syncthreads();
    float alpha = 1.f + sS[0];
    float b1s   = sS[1];

    // ---- LN x2 : 4 threads per token, 32 channels each
    {
        int tt = tid >> 2, q = tid & 3;
        const float4* xp = reinterpret_cast<const float4*>(x + (to + tt) * 128 + q * 32);
        float4 v[8];
#pragma unroll
        for (int i = 0; i < 8; i++) v[i] = xp[i];
        float s = 0.f, ss = 0.f;
#pragma unroll
        for (int i = 0; i < 8; i++) {
            s  += v[i].x + v[i].y + v[i].z + v[i].w;
            ss += v[i].x * v[i].x + v[i].y * v[i].y + v[i].z * v[i].z + v[i].w * v[i].w;
        }
        s  += __shfl_xor_sync(0xffffffffu, s, 1);
        s  += __shfl_xor_sync(0xffffffffu, s, 2);
        ss += __shfl_xor_sync(0xffffffffu, ss, 1);
        ss += __shfl_xor_sync(0xffffffffu, ss, 2);
        float m = s * (1.f / 128.f);
        float rs = rsqrtf(ss * (1.f / 128.f) - m * m + 1e-6f);
        float s2 = 0.f, ss2 = 0.f;
#pragma unroll
        for (int i = 0; i < 8; i++) {
            v[i].x = fmaf(alpha, (v[i].x - m) * rs, b1s);
            v[i].y = fmaf(alpha, (v[i].y - m) * rs, b1s);
            v[i].z = fmaf(alpha, (v[i].z - m) * rs, b1s);
            v[i].w = fmaf(alpha, (v[i].w - m) * rs, b1s);
            s2  += v[i].x + v[i].y + v[i].z + v[i].w;
            ss2 += v[i].x * v[i].x + v[i].y * v[i].y + v[i].z * v[i].z + v[i].w * v[i].w;
        }
        s2  += __shfl_xor_sync(0xffffffffu, s2, 1);
        s2  += __shfl_xor_sync(0xffffffffu, s2, 2);
        ss2 += __shfl_xor_sync(0xffffffffu, ss2, 1);
        ss2 += __shfl_xor_sync(0xffffffffu, ss2, 2);
        float m2 = s2 * (1.f / 128.f);
        float rs2 = rsqrtf(ss2 * (1.f / 128.f) - m2 * m2 + 1e-6f);
        float* Ap = &As[tt * SPAD + q * 32];
#pragma unroll
        for (int i = 0; i < 8; i++) {
            float4 o;
            o.x = cvt_tf32((v[i].x - m2) * rs2);
            o.y = cvt_tf32((v[i].y - m2) * rs2);
            o.z = cvt_tf32((v[i].z - m2) * rs2);
            o.w = cvt_tf32((v[i].w - m2) * rs2);
            *reinterpret_cast<float4*>(Ap + i * 4) = o;
        }
    }
    copy_img(Wimg, g_wimg[0], tid);
    __syncthreads();

    int lane = tid & 31, wid = tid >> 5;
    int g = lane >> 2, t = lane & 3;
    int wm = wid >> 1, wn = wid & 1;
    int row0 = wm * 16, col0 = wn * 64;

    // GEMM1: u = ln2h @ Win
    float c1[8][4];
#pragma unroll
    for (int j = 0; j < 8; j++)
#pragma unroll
        for (int e = 0; e < 4; e++) c1[j][e] = 0.f;
    gemm_16x64_p(As, Wimg, row0, wn, lane, g, t, c1);
    __syncthreads();

    // u = c1 + bin + pos  -> back into As (tf32)
#pragma unroll
    for (int j = 0; j < 8; j++) {
        int n = col0 + 8 * j + 2 * t;
        int r0 = row0 + g, r1 = r0 + 8;
        float2 bb = *reinterpret_cast<const float2*>(bin + n);
        float2 p0 = *reinterpret_cast<const float2*>(pos + (tib + r0) * 128 + n);
        float2 p1 = *reinterpret_cast<const float2*>(pos + (tib + r1) * 128 + n);
        As[r0 * SPAD + n]     = cvt_tf32(c1[j][0] + bb.x + p0.x);
        As[r0 * SPAD + n + 1] = cvt_tf32(c1[j][1] + bb.y + p0.y);
        As[r1 * SPAD + n]     = cvt_tf32(c1[j][2] + bb.x + p1.x);
        As[r1 * SPAD + n + 1] = cvt_tf32(c1[j][3] + bb.y + p1.y);
    }
    copy_img(Wimg, g_wimg[1], tid);
    __syncthreads();

    // GEMM2: input gate
    float gi[8][4];
#pragma unroll
    for (int j = 0; j < 8; j++)
#pragma unroll
        for (int e = 0; e < 4; e++) gi[j][e] = 0.f;
    gemm_16x64_p(As, Wimg, row0, wn, lane, g, t, gi);
#pragma unroll
    for (int j = 0; j < 8; j++) {
        int n = col0 + 8 * j + 2 * t;
        float2 bb = *reinterpret_cast<const float2*>(bi + n);
        gi[j][0] = sigmoidf_(gi[j][0] + bb.x);
        gi[j][1] = sigmoidf_(gi[j][1] + bb.y);
        gi[j][2] = sigmoidf_(gi[j][2] + bb.x);
        gi[j][3] = sigmoidf_(gi[j][3] + bb.y);
    }
    __syncthreads();
    copy_img(Wimg, g_wimg[2], tid);
    __syncthreads();

    // GEMM3: recurrence gate
#pragma unroll
    for (int j = 0; j < 8; j++)
#pragma unroll
        for (int e = 0; e < 4; e++) c1[j][e] = 0.f;
    gemm_16x64_p(As, Wimg, row0, wn, lane, g, t, c1);

    // epilogue: a_t, b_t
#pragma unroll
    for (int j = 0; j < 8; j++) {
        int n = col0 + 8 * j + 2 * t;
        int r0 = row0 + g, r1 = r0 + 8;
        float2 bb = *reinterpret_cast<const float2*>(br + n);
        float la0 = L2A[n], la1 = L2A[n + 1];
        float u00 = As[r0 * SPAD + n], u01 = As[r0 * SPAD + n + 1];
        float u10 = As[r1 * SPAD + n], u11 = As[r1 * SPAD + n + 1];
        float at00 = exp2f(8.f * sigmoidf_(c1[j][0] + bb.x) * la0);
        float at01 = exp2f(8.f * sigmoidf_(c1[j][1] + bb.y) * la1);
        float at10 = exp2f(8.f * sigmoidf_(c1[j][2] + bb.x) * la0);
        float at11 = exp2f(8.f * sigmoidf_(c1[j][3] + bb.y) * la1);
        float bt00 = sqrtf(fmaxf(1.f - at00 * at00, 0.f)) * gi[j][0] * u00;
        float bt01 = sqrtf(fmaxf(1.f - at01 * at01, 0.f)) * gi[j][1] * u01;
        float bt10 = sqrtf(fmaxf(1.f - at10 * at10, 0.f)) * gi[j][2] * u10;
        float bt11 = sqrtf(fmaxf(1.f - at11 * at11, 0.f)) * gi[j][3] * u11;
        int i0 = (to + r0) * 128 + n;
        int i1 = (to + r1) * 128 + n;
        *reinterpret_cast<float2*>(g_at + i0) = make_float2(at00, at01);
        *reinterpret_cast<float2*>(g_at + i1) = make_float2(at10, at11);
        *reinterpret_cast<float2*>(g_bt + i0) = make_float2(bt00, bt01);
        *reinterpret_cast<float2*>(g_bt + i1) = make_float2(bt10, bt11);
    }
}

// ---------------- K2a: per-chunk scan states -----------------------------
__global__ __launch_bounds__(256) void k2a_chunk()
{
    int blk = blockIdx.x;
    int b = blk >> 6, ci = blk & 63;
    int tid = threadIdx.x;
    int dir = tid >> 7, h = tid & 127;
    int base = ((b << 13) + (ci << 7)) * 128 + h;
    float Ap = 1.f, Bv = 0.f;
    if (dir == 0) {
#pragma unroll 4
        for (int s = 0; s < CS; s++) {
            int idx = base + (s << 7);
            float a = g_at[idx], bb = g_bt[idx];
            Ap *= a;
            Bv = fmaf(a, Bv, bb);
        }
    } else {
#pragma unroll 4
        for (int s = CS - 1; s >= 0; s--) {
            int idx = base + (s << 7);
            float a = g_at[idx], bb = g_bt[idx];
            Ap *= a;
            Bv = fmaf(a, Bv, bb);
        }
    }
    g_stA[dir][b][ci][h] = Ap;
    g_stB[dir][b][ci][h] = Bv;
}

// ---------------- K3: chunk-prefix + re-scan + out-GEMM + residual -------
__global__ __launch_bounds__(256) void k3_scan_out(
    const float* __restrict__ x, const float* __restrict__ cvec,
    const float* __restrict__ g1w, const float* __restrict__ g1b,
    const float* __restrict__ bout, float* __restrict__ out)
{
    extern __shared__ float sm[];
    float*  HF   = sm;                   // 128*SPAD
    float*  HB   = sm + 128 * SPAD;      // 128*SPAD
    float2* Wimg = reinterpret_cast<float2*>(sm + 256 * SPAD); // 8192 float2
    float*  sG   = sm + 256 * SPAD + 16384;
    int blk = blockIdx.x;
    int b = blk >> 6, ci = blk & 63;
    int tid = threadIdx.x;

    if (tid < 32) {
        float p = dot32(cvec + b * 128, g1w, tid);
        if (tid == 0) sG[0] = p + g1b[0];
    }
    {
        int dir = tid >> 7, h = tid & 127;
        // fold incoming state from preceding chunk states
        float hc = 0.f;
        if (dir == 0) {
            for (int j = 0; j < ci; j++)
                hc = fmaf(g_stA[0][b][j][h], hc, g_stB[0][b][j][h]);
        } else {
            for (int j = NC - 1; j > ci; j--)
                hc = fmaf(g_stA[1][b][j][h], hc, g_stB[1][b][j][h]);
        }
        int base = ((b << 13) + (ci << 7)) * 128 + h;
        if (dir == 0) {
#pragma unroll 4
            for (int s = 0; s < CS; s++) {
                int idx = base + (s << 7);
                hc = fmaf(g_at[idx], hc, g_bt[idx]);
                HF[s * SPAD + h] = cvt_tf32(hc);
            }
        } else {
#pragma unroll 4
            for (int s = CS - 1; s >= 0; s--) {
                int idx = base + (s << 7);
                hc = fmaf(g_at[idx], hc, g_bt[idx]);
                HB[s * SPAD + h] = cvt_tf32(hc);
            }
        }
    }
    copy_img(Wimg, g_wimg[3], tid);
    __syncthreads();

    int lane = tid & 31, wid = tid >> 5;
    int g = lane >> 2, t = lane & 3;
    int wm = wid >> 1, wn = wid & 1;
    int row0 = wm * 32, col0 = wn * 64;
    float c[2][8][4];
#pragma unroll
    for (int m = 0; m < 2; m++)
#pragma unroll
        for (int j = 0; j < 8; j++)
#pragma unroll
            for (int e = 0; e < 4; e++) c[m][j][e] = 0.f;
#pragma unroll
    for (int m = 0; m < 2; m++)
        gemm_16x64_p(HF, Wimg, row0 + 16 * m, wn, lane, g, t, c[m]);
    __syncthreads();
    copy_img(Wimg, g_wimg[4], tid);
    __syncthreads();
#pragma unroll
    for (int m = 0; m < 2; m++)
        gemm_16x64_p(HB, Wimg, row0 + 16 * m, wn, lane, g, t, c[m]);

    float g1 = sG[0];
    int tbase = (b << 13) + (ci << 7);
#pragma unroll
    for (int m = 0; m < 2; m++) {
#pragma unroll
        for (int j = 0; j < 8; j++) {
            int n = col0 + 8 * j + 2 * t;
            int r0 = row0 + 16 * m + g, r1 = r0 + 8;
            float2 bb = *reinterpret_cast<const float2*>(bout + n);
            int i0 = (tbase + r0) * 128 + n;
            int i1 = (tbase + r1) * 128 + n;
            float2 x0 = *reinterpret_cast<const float2*>(x + i0);
            float2 x1 = *reinterpret_cast<const float2*>(x + i1);
            float2 o0, o1;
            o0.x = fmaf(g1, c[m][j][0] + bb.x, x0.x);
            o0.y = fmaf(g1, c[m][j][1] + bb.y, x0.y);
            o1.x = fmaf(g1, c[m][j][2] + bb.x, x1.x);
            o1.y = fmaf(g1, c[m][j][3] + bb.y, x1.y);
            *reinterpret_cast<float2*>(out + i0) = o0;
            *reinterpret_cast<float2*>(out + i1) = o1;
        }
    }
}

// ---------------- K4: cond-LN -> GELU MLP -> gated residual --------------
__global__ __launch_bounds__(256) void k4_mlp(
    float* __restrict__ out, const float* __restrict__ cvec,
    const float* __restrict__ sw2, const float* __restrict__ sb2,
    const float* __restrict__ bw2, const float* __restrict__ bb2,
    const float* __restrict__ g2w, const float* __restrict__ g2b,
    const float* __restrict__ b1v, const float* __restrict__ b2v)
{
    extern __shared__ float sm[];
    float*  HS    = sm;                   // 64*SPAD
    float*  M1c   = sm + 64 * SPAD;       // 64*SPAD
    float2* W1img = reinterpret_cast<float2*>(sm + 128 * SPAD);
    float2* W2img = W1img + 8192;
    float*  sS    = sm + 128 * SPAD + 32768;
    int tid = threadIdx.x;
    int to = blockIdx.x * 64;
    int b = to >> 13;

    if (tid < 32) {
        float p0 = dot32(cvec + b * 128, sw2, tid);
        float p1 = dot32(cvec + b * 128, bw2, tid);
        float p2 = dot32(cvec + b * 128, g2w, tid);
        if (tid == 0) {
            sS[0] = p0 + sb2[0];
            sS[1] = p1 + bb2[0];
            sS[2] = p2 + g2b[0];
        }
    }
    __syncthreads();
    float alpha = 1.f + sS[0];
    float b2s = sS[1], g2 = sS[2];

    // LN: 4 threads per token
    {
        int tt = tid >> 2, q = tid & 3;
        const float4* xp = reinterpret_cast<const float4*>(out + (to + tt) * 128 + q * 32);
        float4 v[8];
#pragma unroll
        for (int i = 0; i < 8; i++) v[i] = xp[i];
        float s = 0.f, ss = 0.f;
#pragma unroll
        for (int i = 0; i < 8; i++) {
            s  += v[i].x + v[i].y + v[i].z + v[i].w;
            ss += v[i].x * v[i].x + v[i].y * v[i].y + v[i].z * v[i].z + v[i].w * v[i].w;
        }
        s  += __shfl_xor_sync(0xffffffffu, s, 1);
        s  += __shfl_xor_sync(0xffffffffu, s, 2);
        ss += __shfl_xor_sync(0xffffffffu, ss, 1);
        ss += __shfl_xor_sync(0xffffffffu, ss, 2);
        float m = s * (1.f / 128.f);
        float rs = rsqrtf(ss * (1.f / 128.f) - m * m + 1e-6f);
        float* hp = &HS[tt * SPAD + q * 32];
#pragma unroll
        for (int i = 0; i < 8; i++) {
            float4 o;
            o.x = cvt_tf32(fmaf(alpha, (v[i].x - m) * rs, b2s));
            o.y = cvt_tf32(fmaf(alpha, (v[i].y - m) * rs, b2s));
            o.z = cvt_tf32(fmaf(alpha, (v[i].z - m) * rs, b2s));
            o.w = cvt_tf32(fmaf(alpha, (v[i].w - m) * rs, b2s));
            *reinterpret_cast<float4*>(hp + i * 4) = o;
        }
    }

    int lane = tid & 31, wid = tid >> 5;
    int g = lane >> 2, t = lane & 3;
    int wm = wid >> 1, wn = wid & 1;
    int row0 = wm * 16, col0 = wn * 64;

    float C2[8][4];
#pragma unroll
    for (int j = 0; j < 8; j++)
#pragma unroll
        for (int e = 0; e < 4; e++) C2[j][e] = 0.f;

    for (int ch = 0; ch < 4; ch++) {
        __syncthreads();
        copy_img(W1img, g_wimg[5 + ch], tid);
        copy_img(W2img, g_wimg[9 + ch], tid);
        __syncthreads();

        float c1[8][4];
#pragma unroll
        for (int j = 0; j < 8; j++)
#pragma unroll
            for (int e = 0; e < 4; e++) c1[j][e] = 0.f;
        gemm_16x64_p(HS, W1img, row0, wn, lane, g, t, c1);

        // gelu -> M1c (tf32)
#pragma unroll
        for (int j = 0; j < 8; j++) {
            int n = col0 + 8 * j + 2 * t;
            int r0 = row0 + g, r1 = r0 + 8;
            float2 bb = *reinterpret_cast<const float2*>(b1v + ch * 128 + n);
            M1c[r0 * SPAD + n]     = cvt_tf32(geluf_(c1[j][0] + bb.x));
            M1c[r0 * SPAD + n + 1] = cvt_tf32(geluf_(c1[j][1] + bb.y));
            M1c[r1 * SPAD + n]     = cvt_tf32(geluf_(c1[j][2] + bb.x));
            M1c[r1 * SPAD + n + 1] = cvt_tf32(geluf_(c1[j][3] + bb.y));
        }
        __syncthreads();
        gemm_16x64_p(M1c, W2img, row0, wn, lane, g, t, C2);
    }

    // epilogue
#pragma unroll
    for (int j = 0; j < 8; j++) {
        int n = col0 + 8 * j + 2 * t;
        int r0 = row0 + g, r1 = r0 + 8;
        float2 bb = *reinterpret_cast<const float2*>(b2v + n);
        int i0 = (to + r0) * 128 + n;
        int i1 = (to + r1) * 128 + n;
        float2 x0 = *reinterpret_cast<const float2*>(out + i0);
        float2 x1 = *reinterpret_cast<const float2*>(out + i1);
        float2 o0, o1;
        o0.x = fmaf(g2, C2[j][0] + bb.x, x0.x);
        o0.y = fmaf(g2, C2[j][1] + bb.y, x0.y);
        o1.x = fmaf(g2, C2[j][2] + bb.x, x1.x);
        o1.y = fmaf(g2, C2[j][3] + bb.y, x1.y);
        *reinterpret_cast<float2*>(out + i0) = o0;
        *reinterpret_cast<float2*>(out + i1) = o1;
    }
}

// ---------------- launch -------------------------------------------------
extern "C" void kernel_launch(void* const* d_in, const int* in_sizes, int n_in,
                              void* d_out, int out_size)
{
    const float* x        = (const float*)d_in[0];
    const float* c        = (const float*)d_in[1];
    const float* cln1_sw  = (const float*)d_in[2];
    const float* cln1_sb  = (const float*)d_in[3];
    const float* cln1_bw  = (const float*)d_in[4];
    const float* cln1_bb  = (const float*)d_in[5];
    const float* gate1_w  = (const float*)d_in[6];
    const float* gate1_b  = (const float*)d_in[7];
    const float* rnn_in_w = (const float*)d_in[8];
    const float* rnn_in_b = (const float*)d_in[9];
    const float* pos_emb  = (const float*)d_in[10];
    const float* rnn_wi   = (const float*)d_in[11];
    const float* rnn_bi   = (const float*)d_in[12];
    const float* rnn_wr   = (const float*)d_in[13];
    const float* rnn_br   = (const float*)d_in[14];
    const float* rnn_a    = (const float*)d_in[15];
    const float* rnn_out_w= (const float*)d_in[16];
    const float* rnn_out_b= (const float*)d_in[17];
    const float* cln2_sw  = (const float*)d_in[18];
    const float* cln2_sb  = (const float*)d_in[19];
    const float* cln2_bw  = (const float*)d_in[20];
    const float* cln2_bb  = (const float*)d_in[21];
    const float* gate2_w  = (const float*)d_in[22];
    const float* gate2_b  = (const float*)d_in[23];
    const float* mlp_w1   = (const float*)d_in[24];
    const float* mlp_b1   = (const float*)d_in[25];
    const float* mlp_w2   = (const float*)d_in[26];
    const float* mlp_b2   = (const float*)d_in[27];
    float* out = (float*)d_out;

    const int SM1 = (64 * SPAD) * 4 + 65536 + 128 * 4 + 32;    // ~101 KB
    const int SM3 = (256 * SPAD) * 4 + 65536 + 32;             // ~205 KB
    const int SM4 = (128 * SPAD) * 4 + 131072 + 32;            // ~201 KB
    cudaFuncSetAttribute(k1_pre,      cudaFuncAttributeMaxDynamicSharedMemorySize, SM1);
    cudaFuncSetAttribute(k3_scan_out, cudaFuncAttributeMaxDynamicSharedMemorySize, SM3);
    cudaFuncSetAttribute(k4_mlp,      cudaFuncAttributeMaxDynamicSharedMemorySize, SM4);

    kp_pack<<<13, 256>>>(rnn_in_w, rnn_wi, rnn_wr, rnn_out_w, mlp_w1, mlp_w2);
    k1_pre<<<1024, 256, SM1>>>(x, c, cln1_sw, cln1_sb, cln1_bw, cln1_bb,
                               rnn_in_b, pos_emb, rnn_bi, rnn_br, rnn_a);
    k2a_chunk<<<512, 256>>>();
    k3_scan_out<<<512, 256, SM3>>>(x, c, gate1_w, gate1_b, rnn_out_b, out);
    k4_mlp<<<1024, 256, SM4>>>(out, c, cln2_sw, cln2_sb, cln2_bw, cln2_bb,
                               gate2_w, gate2_b, mlp_b1, mlp_b2);
}